// round 3
// baseline (speedup 1.0000x reference)
#include <cuda_runtime.h>
#include <math.h>

#define NN   50000
#define NE   800000
#define DIM  128
#define HID  128
#define ODIM 64
#define NL   3
#define NPB  16   // nodes per block in dense kernels (50000 % 16 == 0)

typedef unsigned long long u64;

// Scratch (no allocation allowed)
__device__ float g_h[(size_t)NN * HID];
__device__ float g_agg[(size_t)NN * HID];
__device__ float g_cnt[NN];
// Transposed weights: WT[c][k] = W[k][c]
__device__ float g_inWT[DIM * HID];
__device__ float g_WlT[NL * HID * HID];
__device__ float g_WrT[NL * HID * HID];
__device__ float g_oWT[ODIM * HID];

__device__ __forceinline__ float gelu_f(float x) {
    return 0.5f * x * (1.0f + erff(x * 0.70710678118654752440f));
}

// packed fp32x2 fma: d = a*b + d (lanewise)
__device__ __forceinline__ void ffma2(u64& d, u64 a, u64 b) {
    asm("fma.rn.f32x2 %0, %1, %2, %0;" : "+l"(d) : "l"(a), "l"(b));
}
__device__ __forceinline__ float unpack_sum(u64 v) {
    float lo, hi;
    asm("mov.b64 {%0, %1}, %2;" : "=f"(lo), "=f"(hi) : "l"(v));
    return lo + hi;
}

// ---------------------------------------------------------------------------
// Tiled transpose: out[c][r] = in[r][c], R rows, C cols
// ---------------------------------------------------------------------------
__global__ __launch_bounds__(256) void tp_kernel(
    const float* __restrict__ in, float* __restrict__ out, int R, int C)
{
    __shared__ float t[32][33];
    int bx = blockIdx.x * 32, by = blockIdx.y * 32;
    int x = threadIdx.x, y = threadIdx.y;  // block (32, 8)
#pragma unroll
    for (int i = y; i < 32; i += 8) {
        int rr = by + i, cc = bx + x;
        if (rr < R && cc < C) t[i][x] = in[rr * C + cc];
    }
    __syncthreads();
#pragma unroll
    for (int i = y; i < 32; i += 8) {
        int rr = by + x, cc = bx + i;
        if (rr < R && cc < C) out[cc * R + rr] = t[x][i];
    }
}

// ---------------------------------------------------------------------------
// In-degree count: one thread per edge
// ---------------------------------------------------------------------------
__global__ __launch_bounds__(256) void count_kernel(const int* __restrict__ dst) {
    int e = blockIdx.x * blockDim.x + threadIdx.x;
    if (e < NE) atomicAdd(&g_cnt[dst[e]], 1.0f);
}

// ---------------------------------------------------------------------------
// Fused: layernorm(x) -> @ in_proj + b -> gelu -> g_h
// 16 rows/block of 128 threads; each thread computes 2 cols (col, col+64)
// over 8 rows selected by grp = tid>>6. FFMA2 packed along k.
// ---------------------------------------------------------------------------
__global__ __launch_bounds__(128) void input_kernel(
    const float* __restrict__ x,
    const float* __restrict__ lng, const float* __restrict__ lnb,
    const float* __restrict__ WT,  const float* __restrict__ pb)
{
    __shared__ __align__(16) float sm[NPB][DIM];
    int nb = blockIdx.x * NPB;
    int tid = threadIdx.x, w = tid >> 5, lane = tid & 31;

    // Phase 1: LN, 4 rows per warp
#pragma unroll
    for (int rr = 0; rr < 4; rr++) {
        int r = w + rr * 4;
        int node = nb + r;
        int c = lane * 4;
        float4 v = *(const float4*)(x + (size_t)node * DIM + c);
        float s  = v.x + v.y + v.z + v.w;
        float sq = v.x*v.x + v.y*v.y + v.z*v.z + v.w*v.w;
#pragma unroll
        for (int o = 16; o > 0; o >>= 1) {
            s  += __shfl_xor_sync(0xffffffffu, s,  o);
            sq += __shfl_xor_sync(0xffffffffu, sq, o);
        }
        float m    = s * (1.0f / DIM);
        float rstd = rsqrtf(sq * (1.0f / DIM) - m * m + 1e-5f);
        float4 o4;
        o4.x = (v.x - m) * rstd * lng[c + 0] + lnb[c + 0];
        o4.y = (v.y - m) * rstd * lng[c + 1] + lnb[c + 1];
        o4.z = (v.z - m) * rstd * lng[c + 2] + lnb[c + 2];
        o4.w = (v.w - m) * rstd * lng[c + 3] + lnb[c + 3];
        *(float4*)&sm[r][c] = o4;
    }
    __syncthreads();

    int col = tid & 63;
    int grp = tid >> 6;
    int r0  = grp * 8;

    u64 acc[8][2];
#pragma unroll
    for (int r = 0; r < 8; r++) { acc[r][0] = 0ull; acc[r][1] = 0ull; }

#pragma unroll 4
    for (int k = 0; k < DIM; k += 4) {
        ulonglong2 w0 = *(const ulonglong2*)(WT + (size_t)col        * DIM + k);
        ulonglong2 w1 = *(const ulonglong2*)(WT + (size_t)(col + 64) * DIM + k);
#pragma unroll
        for (int r = 0; r < 8; r++) {
            ulonglong2 hv = *(const ulonglong2*)&sm[r0 + r][k];
            ffma2(acc[r][0], hv.x, w0.x); ffma2(acc[r][0], hv.y, w0.y);
            ffma2(acc[r][1], hv.x, w1.x); ffma2(acc[r][1], hv.y, w1.y);
        }
    }

    float b0 = pb[col], b1 = pb[col + 64];
#pragma unroll
    for (int r = 0; r < 8; r++) {
        int node = nb + r0 + r;
        g_h[(size_t)node * HID + col]      = gelu_f(unpack_sum(acc[r][0]) + b0);
        g_h[(size_t)node * HID + col + 64] = gelu_f(unpack_sum(acc[r][1]) + b1);
    }
}

// ---------------------------------------------------------------------------
// Scatter-add: warp per edge, vector red.global.add.v4.f32
// ---------------------------------------------------------------------------
__global__ __launch_bounds__(256) void scatter_kernel(
    const int* __restrict__ src, const int* __restrict__ dst)
{
    int idx = blockIdx.x * blockDim.x + threadIdx.x;
    int e = idx >> 5;
    if (e >= NE) return;
    int c = (idx & 31) * 4;
    int s = __ldg(src + e);
    int d = __ldg(dst + e);
    float4 v = *(const float4*)(g_h + (size_t)s * HID + c);
    float* p = g_agg + (size_t)d * HID + c;
    asm volatile("red.global.add.v4.f32 [%0], {%1, %2, %3, %4};"
                 :: "l"(p), "f"(v.x), "f"(v.y), "f"(v.z), "f"(v.w)
                 : "memory");
}

// ---------------------------------------------------------------------------
// Fused SAGE tail: mean@Wl + bl + h@Wr -> LN -> gelu -> +h -> g_h
// 16 rows/block, 2 cols/thread, FFMA2 packed along k.
// ---------------------------------------------------------------------------
__global__ __launch_bounds__(128) void combine_kernel(
    const float* __restrict__ WlT, const float* __restrict__ bl,
    const float* __restrict__ WrT,
    const float* __restrict__ ng,  const float* __restrict__ nbeta)
{
    __shared__ __align__(16) float sm_m[NPB][DIM];
    __shared__ __align__(16) float sm_r[NPB][DIM];
    int nb = blockIdx.x * NPB;
    int tid = threadIdx.x, w = tid >> 5, lane = tid & 31;

    // Phase 1: mean = agg/max(cnt,1), root = h -> smem (4 rows per warp)
#pragma unroll
    for (int rr = 0; rr < 4; rr++) {
        int r = w + rr * 4;
        int node = nb + r;
        int c = lane * 4;
        float inv = 1.0f / fmaxf(g_cnt[node], 1.0f);
        float4 a = *(const float4*)(g_agg + (size_t)node * HID + c);
        float4 h = *(const float4*)(g_h   + (size_t)node * HID + c);
        a.x *= inv; a.y *= inv; a.z *= inv; a.w *= inv;
        *(float4*)&sm_m[r][c] = a;
        *(float4*)&sm_r[r][c] = h;
    }
    __syncthreads();

    // Phase 2: dual matvec, 2 cols x 8 rows per thread
    int col = tid & 63;
    int grp = tid >> 6;
    int r0  = grp * 8;

    u64 acc[8][2];
#pragma unroll
    for (int r = 0; r < 8; r++) { acc[r][0] = 0ull; acc[r][1] = 0ull; }

#pragma unroll 4
    for (int k = 0; k < DIM; k += 4) {
        ulonglong2 wl0 = *(const ulonglong2*)(WlT + (size_t)col        * DIM + k);
        ulonglong2 wl1 = *(const ulonglong2*)(WlT + (size_t)(col + 64) * DIM + k);
        ulonglong2 wr0 = *(const ulonglong2*)(WrT + (size_t)col        * DIM + k);
        ulonglong2 wr1 = *(const ulonglong2*)(WrT + (size_t)(col + 64) * DIM + k);
#pragma unroll
        for (int r = 0; r < 8; r++) {
            ulonglong2 mv = *(const ulonglong2*)&sm_m[r0 + r][k];
            ulonglong2 hv = *(const ulonglong2*)&sm_r[r0 + r][k];
            ffma2(acc[r][0], mv.x, wl0.x); ffma2(acc[r][0], mv.y, wl0.y);
            ffma2(acc[r][0], hv.x, wr0.x); ffma2(acc[r][0], hv.y, wr0.y);
            ffma2(acc[r][1], mv.x, wl1.x); ffma2(acc[r][1], mv.y, wl1.y);
            ffma2(acc[r][1], hv.x, wr1.x); ffma2(acc[r][1], hv.y, wr1.y);
        }
    }
    __syncthreads();   // everyone done reading sm_m before overwrite

    float b0 = bl[col], b1 = bl[col + 64];
#pragma unroll
    for (int r = 0; r < 8; r++) {
        sm_m[r0 + r][col]      = unpack_sum(acc[r][0]) + b0;
        sm_m[r0 + r][col + 64] = unpack_sum(acc[r][1]) + b1;
    }
    __syncthreads();

    // Phase 3: LN + gelu + residual -> g_h (4 rows per warp)
#pragma unroll
    for (int rr = 0; rr < 4; rr++) {
        int r = w + rr * 4;
        int node = nb + r;
        int c = lane * 4;
        float4 v = *(const float4*)&sm_m[r][c];
        float s  = v.x + v.y + v.z + v.w;
        float sq = v.x*v.x + v.y*v.y + v.z*v.z + v.w*v.w;
#pragma unroll
        for (int o = 16; o > 0; o >>= 1) {
            s  += __shfl_xor_sync(0xffffffffu, s,  o);
            sq += __shfl_xor_sync(0xffffffffu, sq, o);
        }
        float m    = s * (1.0f / HID);
        float rstd = rsqrtf(sq * (1.0f / HID) - m * m + 1e-5f);
        float4 hres = *(const float4*)&sm_r[r][c];
        float4 o4;
        o4.x = gelu_f((v.x - m) * rstd * ng[c + 0] + nbeta[c + 0]) + hres.x;
        o4.y = gelu_f((v.y - m) * rstd * ng[c + 1] + nbeta[c + 1]) + hres.y;
        o4.z = gelu_f((v.z - m) * rstd * ng[c + 2] + nbeta[c + 2]) + hres.z;
        o4.w = gelu_f((v.w - m) * rstd * ng[c + 3] + nbeta[c + 3]) + hres.w;
        *(float4*)(g_h + (size_t)node * HID + c) = o4;
    }
}

// ---------------------------------------------------------------------------
// Fused: layernorm(h) @ out_proj + b -> out
// 16 rows/block, 1 col x 8 rows per thread (64 cols), FFMA2 packed along k.
// ---------------------------------------------------------------------------
__global__ __launch_bounds__(128) void final_kernel(
    const float* __restrict__ lng, const float* __restrict__ lnb,
    const float* __restrict__ WT,  const float* __restrict__ pb,
    float* __restrict__ out)
{
    __shared__ __align__(16) float sm[NPB][DIM];
    int nb = blockIdx.x * NPB;
    int tid = threadIdx.x, w = tid >> 5, lane = tid & 31;

#pragma unroll
    for (int rr = 0; rr < 4; rr++) {
        int r = w + rr * 4;
        int node = nb + r;
        int c = lane * 4;
        float4 v = *(const float4*)(g_h + (size_t)node * HID + c);
        float s  = v.x + v.y + v.z + v.w;
        float sq = v.x*v.x + v.y*v.y + v.z*v.z + v.w*v.w;
#pragma unroll
        for (int o = 16; o > 0; o >>= 1) {
            s  += __shfl_xor_sync(0xffffffffu, s,  o);
            sq += __shfl_xor_sync(0xffffffffu, sq, o);
        }
        float m    = s * (1.0f / HID);
        float rstd = rsqrtf(sq * (1.0f / HID) - m * m + 1e-5f);
        float4 o4;
        o4.x = (v.x - m) * rstd * lng[c + 0] + lnb[c + 0];
        o4.y = (v.y - m) * rstd * lng[c + 1] + lnb[c + 1];
        o4.z = (v.z - m) * rstd * lng[c + 2] + lnb[c + 2];
        o4.w = (v.w - m) * rstd * lng[c + 3] + lnb[c + 3];
        *(float4*)&sm[r][c] = o4;
    }
    __syncthreads();

    int col = tid & 63;
    int grp = tid >> 6;
    int r0  = grp * 8;

    u64 acc[8];
#pragma unroll
    for (int r = 0; r < 8; r++) acc[r] = 0ull;

#pragma unroll 4
    for (int k = 0; k < HID; k += 4) {
        ulonglong2 w0 = *(const ulonglong2*)(WT + (size_t)col * HID + k);
#pragma unroll
        for (int r = 0; r < 8; r++) {
            ulonglong2 hv = *(const ulonglong2*)&sm[r0 + r][k];
            ffma2(acc[r], hv.x, w0.x); ffma2(acc[r], hv.y, w0.y);
        }
    }

    float b0 = pb[col];
#pragma unroll
    for (int r = 0; r < 8; r++) {
        int node = nb + r0 + r;
        out[(size_t)node * ODIM + col] = unpack_sum(acc[r]) + b0;
    }
}

// ---------------------------------------------------------------------------
extern "C" void kernel_launch(void* const* d_in, const int* in_sizes, int n_in,
                              void* d_out, int out_size)
{
    const float* x     = (const float*)d_in[0];
    const int*   ei    = (const int*)  d_in[1];
    const float* in_g  = (const float*)d_in[2];
    const float* in_b  = (const float*)d_in[3];
    const float* inW   = (const float*)d_in[4];
    const float* inPb  = (const float*)d_in[5];
    const float* Wl    = (const float*)d_in[6];
    const float* bl    = (const float*)d_in[7];
    const float* Wr    = (const float*)d_in[8];
    const float* ng    = (const float*)d_in[9];
    const float* nbta  = (const float*)d_in[10];
    const float* og    = (const float*)d_in[11];
    const float* ob    = (const float*)d_in[12];
    const float* oW    = (const float*)d_in[13];
    const float* oPb   = (const float*)d_in[14];
    float* out = (float*)d_out;

    const int* src = ei;
    const int* dst = ei + NE;

    void* cntp = nullptr;
    void* aggp = nullptr;
    void* inWTp = nullptr;
    void* WlTp = nullptr;
    void* WrTp = nullptr;
    void* oWTp = nullptr;
    cudaGetSymbolAddress(&cntp,  g_cnt);
    cudaGetSymbolAddress(&aggp,  g_agg);
    cudaGetSymbolAddress(&inWTp, g_inWT);
    cudaGetSymbolAddress(&WlTp,  g_WlT);
    cudaGetSymbolAddress(&WrTp,  g_WrT);
    cudaGetSymbolAddress(&oWTp,  g_oWT);
    float* inWT = (float*)inWTp;
    float* WlT  = (float*)WlTp;
    float* WrT  = (float*)WrTp;
    float* oWT  = (float*)oWTp;

    const int nblk = NN / NPB;                // 3125 (exact)
    const int sblk = (NE * 32 + 255) / 256;   // 100000

    // Weight transposes (cheap, once per launch)
    {
        dim3 b(32, 8);
        dim3 g128(4, 4);  // 128x128
        tp_kernel<<<g128, b>>>(inW, inWT, DIM, HID);
        for (int l = 0; l < NL; l++) {
            tp_kernel<<<g128, b>>>(Wl + (size_t)l * HID * HID, WlT + (size_t)l * HID * HID, HID, HID);
            tp_kernel<<<g128, b>>>(Wr + (size_t)l * HID * HID, WrT + (size_t)l * HID * HID, HID, HID);
        }
        dim3 g64(2, 4);   // 128x64
        tp_kernel<<<g64, b>>>(oW, oWT, HID, ODIM);
    }

    cudaMemsetAsync(cntp, 0, NN * sizeof(float));
    count_kernel<<<(NE + 255) / 256, 256>>>(dst);
    input_kernel<<<nblk, 128>>>(x, in_g, in_b, inWT, inPb);

    for (int l = 0; l < NL; l++) {
        cudaMemsetAsync(aggp, 0, (size_t)NN * HID * sizeof(float));
        scatter_kernel<<<sblk, 256>>>(src, dst);
        combine_kernel<<<nblk, 128>>>(WlT + (size_t)l * HID * HID,
                                      bl + l * HID,
                                      WrT + (size_t)l * HID * HID,
                                      ng + l * HID,
                                      nbta + l * HID);
    }

    final_kernel<<<nblk, 128>>>(og, ob, oWT, oPb, out);
}